// round 2
// baseline (speedup 1.0000x reference)
#include <cuda_runtime.h>
#include <cstdint>

#define NN 100000
#define EP 1000000
#define EN 500000

// ---------------- scratch (device globals: no allocations allowed) ----------
__device__ __align__(256) float g_aggA[NN * 64];   // pos-sourced aggregation sums
__device__ __align__(256) float g_aggB[NN * 64];   // neg-sourced aggregation sums
__device__ __align__(256) float g_z[NN * 64];      // layer1 output, then layer2 output (in place)
__device__ __align__(256) float g_dpos[NN];
__device__ __align__(256) float g_dneg[NN];

// ---------------- helpers ----------------------------------------------------
__device__ __forceinline__ float tanha(float x) {
    float r;
    asm("tanh.approx.f32 %0, %1;" : "=f"(r) : "f"(x));
    return r;
}

__device__ __forceinline__ void red4(float* addr, float4 v) {
    asm volatile("red.global.add.v4.f32 [%0], {%1, %2, %3, %4};"
                 :: "l"(addr), "f"(v.x), "f"(v.y), "f"(v.z), "f"(v.w)
                 : "memory");
}

// ---------------- zero kernels ----------------------------------------------
__global__ void zero_all_kernel() {
    int i = blockIdx.x * blockDim.x + threadIdx.x;
    float4 z = make_float4(0.f, 0.f, 0.f, 0.f);
    if (i < NN * 16) {
        reinterpret_cast<float4*>(g_aggA)[i] = z;
        reinterpret_cast<float4*>(g_aggB)[i] = z;
    }
    if (i < NN) {
        g_dpos[i] = 0.f;
        g_dneg[i] = 0.f;
    }
}

__global__ void zero_agg_kernel() {
    int i = blockIdx.x * blockDim.x + threadIdx.x;
    float4 z = make_float4(0.f, 0.f, 0.f, 0.f);
    if (i < NN * 16) {
        reinterpret_cast<float4*>(g_aggA)[i] = z;
        reinterpret_cast<float4*>(g_aggB)[i] = z;
    }
}

// ---------------- degree sums ------------------------------------------------
__global__ void degree_kernel(const int* __restrict__ pei, const int* __restrict__ nei,
                              const float* __restrict__ pw, const float* __restrict__ nw) {
    int t = blockIdx.x * blockDim.x + threadIdx.x;
    if (t < EP) {
        atomicAdd(&g_dpos[pei[EP + t]], pw[t]);
    } else if (t < EP + EN) {
        int e = t - EP;
        atomicAdd(&g_dneg[nei[EN + e]], nw[e]);
    }
}

// ---------------- edge scatter (weighted sum) --------------------------------
// 16 threads per edge; each thread handles one float4 chunk (64 floats/row).
// target: 0 -> g_aggA, 1 -> g_aggB.
// use_z: 0 -> read features from x (kernel arg), 1 -> read from device-global g_z.
// swap: dest chunk c reads source chunk c^8 (layer-2 neg edges swap zp/zn halves).
__global__ void scatter_kernel(const int* __restrict__ ei, const float* __restrict__ w,
                               const float4* __restrict__ xfeat, int E,
                               int target, int use_z, int swap) {
    int t = blockIdx.x * blockDim.x + threadIdx.x;
    int e = t >> 4;
    if (e >= E) return;
    int c = t & 15;
    int src = ei[e];
    int dst = ei[E + e];
    float wt = w[e];
    int sc = c ^ (swap << 3);
    const float4* feat = use_z ? reinterpret_cast<const float4*>(g_z) : xfeat;
    float4 v = feat[src * 16 + sc];
    v.x *= wt; v.y *= wt; v.z *= wt; v.w *= wt;
    float* base = target ? g_aggB : g_aggA;
    red4(base + dst * 64 + c * 4, v);
}

// ---------------- layer 1: z = tanh([ap,x]@w1p+b1p | [an,x]@w1n+b1n) ---------
__global__ __launch_bounds__(128) void layer1_kernel(
    const float4* __restrict__ x4,
    const float* __restrict__ w1p, const float* __restrict__ b1p,
    const float* __restrict__ w1n, const float* __restrict__ b1n) {
    __shared__ float sWp[128 * 32];
    __shared__ float sWn[128 * 32];
    for (int i = threadIdx.x; i < 128 * 32; i += 128) {
        sWp[i] = w1p[i];
        sWn[i] = w1n[i];
    }
    __syncthreads();

    int n = blockIdx.x * 128 + threadIdx.x;
    if (n >= NN) return;

    float invp = 1.f / fmaxf(g_dpos[n], 1e-12f);
    float invn = 1.f / fmaxf(g_dneg[n], 1e-12f);

    float aP[32], aN[32];
#pragma unroll
    for (int j = 0; j < 32; j++) { aP[j] = b1p[j]; aN[j] = b1n[j]; }

    const float4* rA = reinterpret_cast<const float4*>(g_aggA) + n * 16;
    const float4* rB = reinterpret_cast<const float4*>(g_aggB) + n * 16;
    const float4* rX = x4 + n * 16;

#pragma unroll 1
    for (int k4 = 0; k4 < 16; k4++) {
        float4 a = rA[k4];
        float4 b = rB[k4];
        float4 xv = rX[k4];
        float av[4] = { a.x * invp, a.y * invp, a.z * invp, a.w * invp };
        float bv[4] = { b.x * invn, b.y * invn, b.z * invn, b.w * invn };
        float xe[4] = { xv.x, xv.y, xv.z, xv.w };
#pragma unroll
        for (int kk = 0; kk < 4; kk++) {
            int k = k4 * 4 + kk;
            const float4* wpA = reinterpret_cast<const float4*>(sWp + k * 32);
            const float4* wpX = reinterpret_cast<const float4*>(sWp + (64 + k) * 32);
            const float4* wnA = reinterpret_cast<const float4*>(sWn + k * 32);
            const float4* wnX = reinterpret_cast<const float4*>(sWn + (64 + k) * 32);
#pragma unroll
            for (int j4 = 0; j4 < 8; j4++) {
                float4 wp = wpA[j4];
                float4 wx = wpX[j4];
                float4 wn = wnA[j4];
                float4 wq = wnX[j4];
                aP[4 * j4 + 0] += av[kk] * wp.x + xe[kk] * wx.x;
                aP[4 * j4 + 1] += av[kk] * wp.y + xe[kk] * wx.y;
                aP[4 * j4 + 2] += av[kk] * wp.z + xe[kk] * wx.z;
                aP[4 * j4 + 3] += av[kk] * wp.w + xe[kk] * wx.w;
                aN[4 * j4 + 0] += bv[kk] * wn.x + xe[kk] * wq.x;
                aN[4 * j4 + 1] += bv[kk] * wn.y + xe[kk] * wq.y;
                aN[4 * j4 + 2] += bv[kk] * wn.z + xe[kk] * wq.z;
                aN[4 * j4 + 3] += bv[kk] * wn.w + xe[kk] * wq.w;
            }
        }
    }

    float4* zr = reinterpret_cast<float4*>(g_z + (size_t)n * 64);
#pragma unroll
    for (int j4 = 0; j4 < 8; j4++) {
        zr[j4] = make_float4(tanha(aP[4 * j4 + 0]), tanha(aP[4 * j4 + 1]),
                             tanha(aP[4 * j4 + 2]), tanha(aP[4 * j4 + 3]));
        zr[8 + j4] = make_float4(tanha(aN[4 * j4 + 0]), tanha(aN[4 * j4 + 1]),
                                 tanha(aN[4 * j4 + 2]), tanha(aN[4 * j4 + 3]));
    }
}

// ---------------- layer 2: z2 = tanh([A1,A2,zp]@w2p+b2p | [A3,A4,zn]@w2n+b2n)
// A1 = aggA[0:32]*invp, A3 = aggA[32:64]*invp  (pos-sourced)
// A2 = aggB[0:32]*invn, A4 = aggB[32:64]*invn  (neg-sourced, halves pre-swapped)
// Writes z2 back into g_z (each thread reads its row fully before writing it).
__global__ __launch_bounds__(128) void layer2_kernel(
    const float* __restrict__ w2p, const float* __restrict__ b2p,
    const float* __restrict__ w2n, const float* __restrict__ b2n) {
    __shared__ float sP[96 * 32];
    __shared__ float sN[96 * 32];
    for (int i = threadIdx.x; i < 96 * 32; i += 128) {
        sP[i] = w2p[i];
        sN[i] = w2n[i];
    }
    __syncthreads();

    int n = blockIdx.x * 128 + threadIdx.x;
    if (n >= NN) return;

    float invp = 1.f / fmaxf(g_dpos[n], 1e-12f);
    float invn = 1.f / fmaxf(g_dneg[n], 1e-12f);

    float aP[32], aN[32];
#pragma unroll
    for (int j = 0; j < 32; j++) { aP[j] = b2p[j]; aN[j] = b2n[j]; }

    const float4* rA = reinterpret_cast<const float4*>(g_aggA) + n * 16;
    const float4* rB = reinterpret_cast<const float4*>(g_aggB) + n * 16;
    const float4* rZ = reinterpret_cast<const float4*>(g_z) + n * 16;

#pragma unroll 1
    for (int k4 = 0; k4 < 8; k4++) {
        float4 A1 = rA[k4];
        float4 A3 = rA[8 + k4];
        float4 A2 = rB[k4];
        float4 A4 = rB[8 + k4];
        float4 zp = rZ[k4];
        float4 zn = rZ[8 + k4];
        float a1[4] = { A1.x * invp, A1.y * invp, A1.z * invp, A1.w * invp };
        float a3[4] = { A3.x * invp, A3.y * invp, A3.z * invp, A3.w * invp };
        float a2[4] = { A2.x * invn, A2.y * invn, A2.z * invn, A2.w * invn };
        float a4[4] = { A4.x * invn, A4.y * invn, A4.z * invn, A4.w * invn };
        float zpv[4] = { zp.x, zp.y, zp.z, zp.w };
        float znv[4] = { zn.x, zn.y, zn.z, zn.w };
#pragma unroll
        for (int kk = 0; kk < 4; kk++) {
            int k = k4 * 4 + kk;
            const float4* p0 = reinterpret_cast<const float4*>(sP + k * 32);
            const float4* p1 = reinterpret_cast<const float4*>(sP + (32 + k) * 32);
            const float4* p2 = reinterpret_cast<const float4*>(sP + (64 + k) * 32);
            const float4* q0 = reinterpret_cast<const float4*>(sN + k * 32);
            const float4* q1 = reinterpret_cast<const float4*>(sN + (32 + k) * 32);
            const float4* q2 = reinterpret_cast<const float4*>(sN + (64 + k) * 32);
#pragma unroll
            for (int j4 = 0; j4 < 8; j4++) {
                float4 w0 = p0[j4], w1 = p1[j4], w2 = p2[j4];
                aP[4 * j4 + 0] += a1[kk] * w0.x + a2[kk] * w1.x + zpv[kk] * w2.x;
                aP[4 * j4 + 1] += a1[kk] * w0.y + a2[kk] * w1.y + zpv[kk] * w2.y;
                aP[4 * j4 + 2] += a1[kk] * w0.z + a2[kk] * w1.z + zpv[kk] * w2.z;
                aP[4 * j4 + 3] += a1[kk] * w0.w + a2[kk] * w1.w + zpv[kk] * w2.w;
                float4 v0 = q0[j4], v1 = q1[j4], v2 = q2[j4];
                aN[4 * j4 + 0] += a3[kk] * v0.x + a4[kk] * v1.x + znv[kk] * v2.x;
                aN[4 * j4 + 1] += a3[kk] * v0.y + a4[kk] * v1.y + znv[kk] * v2.y;
                aN[4 * j4 + 2] += a3[kk] * v0.z + a4[kk] * v1.z + znv[kk] * v2.z;
                aN[4 * j4 + 3] += a3[kk] * v0.w + a4[kk] * v1.w + znv[kk] * v2.w;
            }
        }
    }

    float4* zr = reinterpret_cast<float4*>(g_z + (size_t)n * 64);
#pragma unroll
    for (int j4 = 0; j4 < 8; j4++) {
        zr[j4] = make_float4(tanha(aP[4 * j4 + 0]), tanha(aP[4 * j4 + 1]),
                             tanha(aP[4 * j4 + 2]), tanha(aP[4 * j4 + 3]));
        zr[8 + j4] = make_float4(tanha(aN[4 * j4 + 0]), tanha(aN[4 * j4 + 1]),
                                 tanha(aN[4 * j4 + 2]), tanha(aN[4 * j4 + 3]));
    }
}

// ---------------- layer 3: out = tanh(z2 @ wout + bout) ----------------------
__global__ __launch_bounds__(128) void layer3_kernel(
    const float* __restrict__ wout, const float* __restrict__ bout,
    float* __restrict__ out) {
    __shared__ float sO[64 * 64];
    for (int i = threadIdx.x; i < 64 * 64; i += 128) sO[i] = wout[i];
    __syncthreads();

    int n = blockIdx.x * 128 + threadIdx.x;
    if (n >= NN) return;

    float o[64];
#pragma unroll
    for (int j = 0; j < 64; j++) o[j] = bout[j];

    const float4* rz = reinterpret_cast<const float4*>(g_z) + n * 16;
#pragma unroll 1
    for (int k4 = 0; k4 < 16; k4++) {
        float4 zc = rz[k4];
        float zv[4] = { zc.x, zc.y, zc.z, zc.w };
#pragma unroll
        for (int kk = 0; kk < 4; kk++) {
            const float4* wr = reinterpret_cast<const float4*>(sO + (k4 * 4 + kk) * 64);
#pragma unroll
            for (int j4 = 0; j4 < 16; j4++) {
                float4 w = wr[j4];
                o[4 * j4 + 0] += zv[kk] * w.x;
                o[4 * j4 + 1] += zv[kk] * w.y;
                o[4 * j4 + 2] += zv[kk] * w.z;
                o[4 * j4 + 3] += zv[kk] * w.w;
            }
        }
    }

    float4* orow = reinterpret_cast<float4*>(out + (size_t)n * 64);
#pragma unroll
    for (int j4 = 0; j4 < 16; j4++) {
        orow[j4] = make_float4(tanha(o[4 * j4 + 0]), tanha(o[4 * j4 + 1]),
                               tanha(o[4 * j4 + 2]), tanha(o[4 * j4 + 3]));
    }
}

// ---------------- launch -----------------------------------------------------
extern "C" void kernel_launch(void* const* d_in, const int* in_sizes, int n_in,
                              void* d_out, int out_size) {
    const int*   pei  = (const int*)d_in[0];
    const int*   nei  = (const int*)d_in[1];
    const float* pw   = (const float*)d_in[2];
    const float* nw   = (const float*)d_in[3];
    const float* x    = (const float*)d_in[4];
    const float* w1p  = (const float*)d_in[5];
    const float* b1p  = (const float*)d_in[6];
    const float* w1n  = (const float*)d_in[7];
    const float* b1n  = (const float*)d_in[8];
    const float* w2p  = (const float*)d_in[9];
    const float* b2p  = (const float*)d_in[10];
    const float* w2n  = (const float*)d_in[11];
    const float* b2n  = (const float*)d_in[12];
    const float* wout = (const float*)d_in[13];
    const float* bout = (const float*)d_in[14];
    float* out = (float*)d_out;

    const int ZB = (NN * 16 + 255) / 256;
    const int DB = (EP + EN + 255) / 256;
    const int SPB = (EP * 16 + 255) / 256;
    const int SNB = (EN * 16 + 255) / 256;
    const int LB = (NN + 127) / 128;

    // Degree sums + layer-1 aggregation of x
    zero_all_kernel<<<ZB, 256>>>();
    degree_kernel<<<DB, 256>>>(pei, nei, pw, nw);
    scatter_kernel<<<SPB, 256>>>(pei, pw, (const float4*)x, EP, 0, 0, 0);
    scatter_kernel<<<SNB, 256>>>(nei, nw, (const float4*)x, EN, 1, 0, 0);
    layer1_kernel<<<LB, 128>>>((const float4*)x, w1p, b1p, w1n, b1n);

    // Layer-2 aggregations of z (neg edges swap zp/zn halves)
    zero_agg_kernel<<<ZB, 256>>>();
    scatter_kernel<<<SPB, 256>>>(pei, pw, (const float4*)x, EP, 0, 1, 0);
    scatter_kernel<<<SNB, 256>>>(nei, nw, (const float4*)x, EN, 1, 1, 1);
    layer2_kernel<<<LB, 128>>>(w2p, b2p, w2n, b2n);
    layer3_kernel<<<LB, 128>>>(wout, bout, out);

    (void)in_sizes; (void)n_in; (void)out_size;
}